// round 7
// baseline (speedup 1.0000x reference)
#include <cuda_runtime.h>
#include <cuda_bf16.h>
#include <cstdint>

#define Bz 64
#define Tz 512
#define Iz 128
#define Hz 512
#define Gz 2048          // 4*H
#define BTz (Bz*Tz)      // 32768
#define BHs (Bz*Hz)      // 32768

#define NBLK 128
#define NTHR 512

// Scratch (static device globals)
__device__ float g_XG[(size_t)BTz * Gz];            // 256 MiB: gate projections
__device__ __nv_bfloat16 g_AH[(size_t)BTz * Hz];    // 32 MiB: A hi (x-split, then hseq)
__device__ __nv_bfloat16 g_AL[(size_t)BTz * Hz];    // 32 MiB: A lo
__device__ __nv_bfloat16 g_WH[(size_t)Gz * Hz];     // 2 MiB: W hi
__device__ __nv_bfloat16 g_WL[(size_t)Gz * Hz];     // 2 MiB: W lo
__device__ float g_PART[8 * Gz * Bz];               // split-K partials
__device__ float g_HT[Hz * Bz];                     // transposed hidden state
__device__ unsigned g_count;
__device__ unsigned g_sense;

// ---------------- grid barrier (sense reversal) ----------------
__device__ __forceinline__ void grid_barrier(unsigned sense_val) {
    __syncthreads();
    if (threadIdx.x == 0) {
        __threadfence();
        unsigned arr = atomicAdd(&g_count, 1u);
        if (arr == NBLK - 1) {
            g_count = 0;
            __threadfence();
            asm volatile("st.release.gpu.u32 [%0], %1;" ::
                         "l"(&g_sense), "r"(sense_val) : "memory");
        } else {
            unsigned v;
            do {
                asm volatile("ld.acquire.gpu.u32 %0, [%1];"
                             : "=r"(v) : "l"(&g_sense) : "memory");
            } while (v != sense_val);
        }
    }
    __syncthreads();
}

// ---------------- async-copy / mma helpers ----------------
__device__ __forceinline__ void cp_async16(void* dst_smem, const void* src_gmem) {
    unsigned d = (unsigned)__cvta_generic_to_shared(dst_smem);
    asm volatile("cp.async.cg.shared.global [%0], [%1], 16;\n"
                 :: "r"(d), "l"(src_gmem));
}
#define CP_COMMIT() asm volatile("cp.async.commit_group;\n" ::: "memory")
#define CP_WAIT0()  asm volatile("cp.async.wait_group 0;\n" ::: "memory")
#define CP_WAIT1()  asm volatile("cp.async.wait_group 1;\n" ::: "memory")

__device__ __forceinline__ void ldsm4(uint32_t* r, const __nv_bfloat16* p) {
    uint32_t a = (uint32_t)__cvta_generic_to_shared(p);
    asm volatile("ldmatrix.sync.aligned.m8n8.x4.shared.b16 {%0,%1,%2,%3}, [%4];"
                 : "=r"(r[0]), "=r"(r[1]), "=r"(r[2]), "=r"(r[3]) : "r"(a));
}

__device__ __forceinline__ void mma16816(float* d, const uint32_t* a, const uint32_t* b) {
    asm volatile(
        "mma.sync.aligned.m16n8k16.row.col.f32.bf16.bf16.f32 "
        "{%0,%1,%2,%3}, {%4,%5,%6,%7}, {%8,%9}, {%0,%1,%2,%3};"
        : "+f"(d[0]), "+f"(d[1]), "+f"(d[2]), "+f"(d[3])
        : "r"(a[0]), "r"(a[1]), "r"(a[2]), "r"(a[3]), "r"(b[0]), "r"(b[1]));
}

// ---------------- fp32 -> bf16 hi/lo split ----------------
__global__ __launch_bounds__(256) void split_kernel(
    const float4* __restrict__ src,
    __nv_bfloat162* __restrict__ hi, __nv_bfloat162* __restrict__ lo, int n4)
{
    int i = blockIdx.x * blockDim.x + threadIdx.x;
    if (i >= n4) return;
    float4 v = src[i];
    float xs[4] = {v.x, v.y, v.z, v.w};
    __nv_bfloat16 h[4], l[4];
#pragma unroll
    for (int k = 0; k < 4; k++) {
        h[k] = __float2bfloat16(xs[k]);
        l[k] = __float2bfloat16(xs[k] - __bfloat162float(h[k]));
    }
    __nv_bfloat162 h0; h0.x = h[0]; h0.y = h[1];
    __nv_bfloat162 h1; h1.x = h[2]; h1.y = h[3];
    __nv_bfloat162 l0; l0.x = l[0]; l0.y = l[1];
    __nv_bfloat162 l1; l1.x = l[2]; l1.y = l[3];
    hi[2 * i] = h0; hi[2 * i + 1] = h1;
    lo[2 * i] = l0; lo[2 * i + 1] = l1;
}

// ---------------- tensor-core input-projection GEMM ----------------
// C[M,2048] = A[M,K] @ W[2048,K]^T + bias0 + bias1, bf16 hi/lo split.
// Block tile 128x128, BK=32, 256 threads (8 warps, 2m x 4n, warp 64x32).
__global__ void __launch_bounds__(256, 1) gemm_tc(
    float* __restrict__ C,
    const __nv_bfloat16* __restrict__ Ah, const __nv_bfloat16* __restrict__ Al,
    const __nv_bfloat16* __restrict__ Wh, const __nv_bfloat16* __restrict__ Wl,
    int K, const float* __restrict__ bias0, const float* __restrict__ bias1)
{
    extern __shared__ __nv_bfloat16 sm[];
    const int ARR = 128 * 40;        // one 128x32 tile, row stride 40 (80B)
    const int STG = 4 * ARR;         // Ah, Al, Wh, Wl
    const int tid = threadIdx.x;
    const int lane = tid & 31, wid = tid >> 5;
    const int wm = wid & 1, wn = wid >> 1;
    const int bn = blockIdx.x, bm = blockIdx.y;

    const __nv_bfloat16* g0 = Ah + (size_t)(bm * 128) * K;
    const __nv_bfloat16* g1 = Al + (size_t)(bm * 128) * K;
    const __nv_bfloat16* g2 = Wh + (size_t)(bn * 128) * K;
    const __nv_bfloat16* g3 = Wl + (size_t)(bn * 128) * K;
    const __nv_bfloat16* gsrc[4] = {g0, g1, g2, g3};

    const int l_r = tid >> 2;        // 0..63
    const int l_c = tid & 3;         // 16B chunk

#define LOAD_STAGE(buf, kt)                                                     \
    {                                                                           \
        _Pragma("unroll")                                                       \
        for (int p = 0; p < 8; p++) {                                           \
            const int arr = p >> 1;                                             \
            const int r = (p & 1) * 64 + l_r;                                   \
            const void* s = gsrc[arr] + (size_t)r * K + (kt) + l_c * 8;         \
            void* d = (char*)(sm + (buf) * STG + arr * ARR + r * 40) + l_c * 16;\
            cp_async16(d, s);                                                   \
        }                                                                       \
        CP_COMMIT();                                                            \
    }

    float acc[4][4][4] = {};
    const int nk = K / 32;

    LOAD_STAGE(0, 0);

    const int a_lrow = (lane < 16) ? lane : lane - 16;
    const int a_cb = (lane < 16) ? 0 : 8;
    const int bgrp = lane >> 3, bwi = lane & 7;
    const int b_nrow = ((bgrp >= 2) ? 8 : 0) + bwi;
    const int b_koff = (bgrp & 1) ? 8 : 0;

    for (int it = 0; it < nk; it++) {
        if (it + 1 < nk) {
            LOAD_STAGE((it + 1) & 1, (it + 1) * 32);
            CP_WAIT1();
        } else {
            CP_WAIT0();
        }
        __syncthreads();
        const __nv_bfloat16* S = sm + (it & 1) * STG;

#pragma unroll
        for (int kk = 0; kk < 32; kk += 16) {
            uint32_t ah[4][4], al[4][4];
#pragma unroll
            for (int mt = 0; mt < 4; mt++) {
                int row = wm * 64 + mt * 16 + a_lrow;
                ldsm4(ah[mt], S + row * 40 + kk + a_cb);
                ldsm4(al[mt], S + ARR + row * 40 + kk + a_cb);
            }
            uint32_t bh[4][2], bl[4][2];
#pragma unroll
            for (int pr = 0; pr < 2; pr++) {
                int nrow = wn * 32 + pr * 16 + b_nrow;
                uint32_t r[4];
                ldsm4(r, S + 2 * ARR + nrow * 40 + kk + b_koff);
                bh[pr * 2][0] = r[0]; bh[pr * 2][1] = r[1];
                bh[pr * 2 + 1][0] = r[2]; bh[pr * 2 + 1][1] = r[3];
                ldsm4(r, S + 3 * ARR + nrow * 40 + kk + b_koff);
                bl[pr * 2][0] = r[0]; bl[pr * 2][1] = r[1];
                bl[pr * 2 + 1][0] = r[2]; bl[pr * 2 + 1][1] = r[3];
            }
#pragma unroll
            for (int mt = 0; mt < 4; mt++)
#pragma unroll
                for (int nt = 0; nt < 4; nt++) {
                    mma16816(acc[mt][nt], ah[mt], bh[nt]);
                    mma16816(acc[mt][nt], ah[mt], bl[nt]);
                    mma16816(acc[mt][nt], al[mt], bh[nt]);
                }
        }
        __syncthreads();
    }

    // epilogue: add biases, write fp32
    const int erow = lane >> 2, ecol = (lane & 3) * 2;
#pragma unroll
    for (int mt = 0; mt < 4; mt++) {
        int gr = bm * 128 + wm * 64 + mt * 16 + erow;
#pragma unroll
        for (int nt = 0; nt < 4; nt++) {
            int gc = bn * 128 + wn * 32 + nt * 8 + ecol;
            float b0v = bias0[gc] + bias1[gc];
            float b1v = bias0[gc + 1] + bias1[gc + 1];
            float2 v0 = make_float2(acc[mt][nt][0] + b0v, acc[mt][nt][1] + b1v);
            float2 v1 = make_float2(acc[mt][nt][2] + b0v, acc[mt][nt][3] + b1v);
            *(float2*)(C + (size_t)gr * Gz + gc) = v0;
            *(float2*)(C + (size_t)(gr + 8) * Gz + gc) = v1;
        }
    }
#undef LOAD_STAGE
}

// ---------------- persistent LSTM layer (Round-4 structure) ----------------
__global__ void __launch_bounds__(NTHR, 1) lstm_layer_persist(
    const float* __restrict__ whh,          // [2048][512]
    const float* __restrict__ xg,           // [B*T][2048] (+biases)
    const float* __restrict__ hxl,
    const float* __restrict__ cxl,
    __nv_bfloat16* __restrict__ hseq_hi,    // [B*T][512] or nullptr
    __nv_bfloat16* __restrict__ hseq_lo,
    float* __restrict__ hn_out,
    float* __restrict__ cn_out)
{
    extern __shared__ float smem[];
    float* w_sT = smem;               // [128 k][64 gcl]
    float* h_s  = smem + 128 * 64;    // [128 k][64 b]

    const int tid = threadIdx.x;
    const int bid = blockIdx.x;
    const int jg = bid >> 2;
    const int ks = bid & 3;
    const int k0 = ks * 128;
    const int jgbase = jg * 16;

    for (int i = tid; i < 64 * 128; i += NTHR) {
        int gcl = i >> 7;
        int k = i & 127;
        int g = gcl >> 4, jj = gcl & 15;
        w_sT[k * 64 + gcl] = whh[(size_t)(g * 512 + jgbase + jj) * Hz + k0 + k];
    }

    const int pb_b = (tid & 255) >> 2;
    const int pb_j = bid * 4 + (tid & 3);
    float c_reg = 0.0f;
    if (tid < 256) {
        c_reg = cxl[pb_b * Hz + pb_j];
        g_HT[pb_j * Bz + pb_b] = hxl[pb_b * Hz + pb_j];
    }

    unsigned sense = 0;
    sense ^= 1; grid_barrier(sense);

    const int kh = tid >> 8;
    const int t8 = tid & 255;
    const int b0 = (t8 & 15) * 4;
    const int gcl0 = (t8 >> 4) * 4;
    const int gc_glob0 = (gcl0 >> 4) * 512 + jgbase + (gcl0 & 15);
    const int zslot = ks * 2 + kh;
    const float* wbase = w_sT + (size_t)kh * 64 * 64;
    const float* hbase = h_s  + (size_t)kh * 64 * 64;

    float hlast = 0.0f;

    for (int t = 0; t < Tz; t++) {
        {
            const float4* src = (const float4*)(g_HT + (size_t)k0 * Bz);
            float4* dst = (float4*)h_s;
#pragma unroll
            for (int i = 0; i < (128 * 64 / 4) / NTHR; i++)
                dst[tid + i * NTHR] = src[tid + i * NTHR];
        }
        __syncthreads();

        float acc[4][4] = {};
#pragma unroll 4
        for (int k = 0; k < 64; k++) {
            float4 hv = *(const float4*)(hbase + k * 64 + b0);
            float4 wv = *(const float4*)(wbase + k * 64 + gcl0);
            float hr[4] = {hv.x, hv.y, hv.z, hv.w};
            float wr[4] = {wv.x, wv.y, wv.z, wv.w};
#pragma unroll
            for (int i = 0; i < 4; i++)
#pragma unroll
                for (int j = 0; j < 4; j++)
                    acc[i][j] += wr[i] * hr[j];
        }
#pragma unroll
        for (int i = 0; i < 4; i++) {
            int gc = gc_glob0 + i;
            float4 v = make_float4(acc[i][0], acc[i][1], acc[i][2], acc[i][3]);
            *(float4*)(g_PART + ((size_t)zslot * Gz + gc) * Bz + b0) = v;
        }
        sense ^= 1; grid_barrier(sense);

        if (tid < 256) {
            const float* xr = xg + ((size_t)pb_b * Tz + t) * Gz;
            float gsum[4];
#pragma unroll
            for (int g = 0; g < 4; g++) {
                int gc = g * 512 + pb_j;
                float s = xr[gc];
#pragma unroll
                for (int z = 0; z < 8; z++)
                    s += g_PART[((size_t)z * Gz + gc) * Bz + pb_b];
                gsum[g] = s;
            }
            float ig = 1.0f / (1.0f + expf(-gsum[0]));
            float fg = 1.0f / (1.0f + expf(-gsum[1]));
            float gg = tanhf(gsum[2]);
            float og = 1.0f / (1.0f + expf(-gsum[3]));
            c_reg = fg * c_reg + ig * gg;
            float hnew = og * tanhf(c_reg);
            hlast = hnew;
            g_HT[pb_j * Bz + pb_b] = hnew;
            if (hseq_hi) {
                __nv_bfloat16 hh = __float2bfloat16(hnew);
                __nv_bfloat16 hl = __float2bfloat16(hnew - __bfloat162float(hh));
                size_t off = ((size_t)pb_b * Tz + t) * Hz + pb_j;
                hseq_hi[off] = hh;
                hseq_lo[off] = hl;
            }
        }
        sense ^= 1; grid_barrier(sense);
    }

    if (tid < 256) {
        hn_out[pb_b * Hz + pb_j] = hlast;
        cn_out[pb_b * Hz + pb_j] = c_reg;
    }

    sense ^= 1; grid_barrier(sense);   // total 1026 barriers (even)
}

// ---------------- FC head ----------------
__global__ __launch_bounds__(256) void fc_kernel(
    float* __restrict__ out, const float* __restrict__ h,
    const float* __restrict__ w, const float* __restrict__ bb)
{
    int b = blockIdx.x;
    float s = 0.0f;
    for (int k = threadIdx.x; k < Hz; k += blockDim.x)
        s += h[(size_t)b * Hz + k] * w[k];
#pragma unroll
    for (int o = 16; o > 0; o >>= 1)
        s += __shfl_xor_sync(0xFFFFFFFFu, s, o);
    __shared__ float red[8];
    int wid = threadIdx.x >> 5, lane = threadIdx.x & 31;
    if (lane == 0) red[wid] = s;
    __syncthreads();
    if (threadIdx.x == 0) {
        float t = 0.0f;
#pragma unroll
        for (int i = 0; i < 8; i++) t += red[i];
        out[b] = t + bb[0];
    }
}

extern "C" void kernel_launch(void* const* d_in, const int* in_sizes, int n_in,
                              void* d_out, int out_size) {
    (void)in_sizes; (void)n_in; (void)out_size;
    const float* x    = (const float*)d_in[0];
    const float* hx   = (const float*)d_in[1];
    const float* cx   = (const float*)d_in[2];
    const float* wih0 = (const float*)d_in[3];
    const float* whh0 = (const float*)d_in[4];
    const float* bih0 = (const float*)d_in[5];
    const float* bhh0 = (const float*)d_in[6];
    const float* wih1 = (const float*)d_in[7];
    const float* whh1 = (const float*)d_in[8];
    const float* bih1 = (const float*)d_in[9];
    const float* bhh1 = (const float*)d_in[10];
    const float* fcw  = (const float*)d_in[11];
    const float* fcb  = (const float*)d_in[12];
    float* out = (float*)d_out;

    void *vXG, *vAH, *vAL, *vWH, *vWL;
    cudaGetSymbolAddress(&vXG, g_XG);
    cudaGetSymbolAddress(&vAH, g_AH);
    cudaGetSymbolAddress(&vAL, g_AL);
    cudaGetSymbolAddress(&vWH, g_WH);
    cudaGetSymbolAddress(&vWL, g_WL);
    float* XG = (float*)vXG;
    __nv_bfloat16* AH = (__nv_bfloat16*)vAH;
    __nv_bfloat16* AL = (__nv_bfloat16*)vAL;
    __nv_bfloat16* WH = (__nv_bfloat16*)vWH;
    __nv_bfloat16* WL = (__nv_bfloat16*)vWL;

    const int persist_smem = 2 * 128 * 64 * (int)sizeof(float);        // 64 KB
    const int gemm_smem = 2 * 4 * 128 * 40 * (int)sizeof(__nv_bfloat16); // 80 KB
    static bool attr_set = false;
    if (!attr_set) {
        cudaFuncSetAttribute(lstm_layer_persist,
                             cudaFuncAttributeMaxDynamicSharedMemorySize, persist_smem);
        cudaFuncSetAttribute(gemm_tc,
                             cudaFuncAttributeMaxDynamicSharedMemorySize, gemm_smem);
        attr_set = true;
    }

    // Output packing: [out(64) | hn(2*B*H) | cn(2*B*H)]
    float* hn = out + Bz;
    float* cn = out + Bz + 2 * BHs;

    // ---- Layer 0: split x & w_ih_0, TC GEMM, recurrence ----
    {
        int n4 = (BTz * Iz) / 4;
        split_kernel<<<(n4 + 255) / 256, 256>>>(
            (const float4*)x, (__nv_bfloat162*)AH, (__nv_bfloat162*)AL, n4);
    }
    {
        int n4 = (Gz * Iz) / 4;
        split_kernel<<<(n4 + 255) / 256, 256>>>(
            (const float4*)wih0, (__nv_bfloat162*)WH, (__nv_bfloat162*)WL, n4);
    }
    gemm_tc<<<dim3(Gz / 128, BTz / 128), 256, gemm_smem>>>(
        XG, AH, AL, WH, WL, Iz, bih0, bhh0);
    lstm_layer_persist<<<NBLK, NTHR, persist_smem>>>(
        whh0, XG, hx, cx, AH, AL, hn, cn);   // writes hseq split into AH/AL

    // ---- Layer 1 ----
    {
        int n4 = (Gz * Hz) / 4;
        split_kernel<<<(n4 + 255) / 256, 256>>>(
            (const float4*)wih1, (__nv_bfloat162*)WH, (__nv_bfloat162*)WL, n4);
    }
    gemm_tc<<<dim3(Gz / 128, BTz / 128), 256, gemm_smem>>>(
        XG, AH, AL, WH, WL, Hz, bih1, bhh1);
    lstm_layer_persist<<<NBLK, NTHR, persist_smem>>>(
        whh1, XG, hx + BHs, cx + BHs, nullptr, nullptr, hn + BHs, cn + BHs);

    // ---- FC head ----
    fc_kernel<<<Bz, 256>>>(out, hn + BHs, fcw, fcb);
}

// round 8
// speedup vs baseline: 1.0023x; 1.0023x over previous
#include <cuda_runtime.h>
#include <cuda_bf16.h>
#include <cstdint>

#define Bz 64
#define Tz 512
#define Iz 128
#define Hz 512
#define Gz 2048          // 4*H
#define BTz (Bz*Tz)      // 32768
#define BHs (Bz*Hz)      // 32768

#define NBLK 128
#define NTHR 512

// Scratch (static device globals)
__device__ float g_XG[(size_t)BTz * Gz];            // 256 MiB: gate projections
__device__ __nv_bfloat16 g_AH[(size_t)BTz * Hz];    // 32 MiB: A hi (x-split, then hseq)
__device__ __nv_bfloat16 g_AL[(size_t)BTz * Hz];    // 32 MiB: A lo
__device__ __nv_bfloat16 g_WH[(size_t)Gz * Hz];     // 2 MiB: W hi
__device__ __nv_bfloat16 g_WL[(size_t)Gz * Hz];     // 2 MiB: W lo
__device__ float g_PART[8 * Gz * Bz];               // split-K partials
__device__ float g_HT[Hz * Bz];                     // transposed hidden state
__device__ unsigned g_count;
__device__ unsigned g_sense;

// ---------------- grid barrier (sense reversal) ----------------
__device__ __forceinline__ void grid_barrier(unsigned sense_val) {
    __syncthreads();
    if (threadIdx.x == 0) {
        __threadfence();
        unsigned arr = atomicAdd(&g_count, 1u);
        if (arr == NBLK - 1) {
            g_count = 0;
            __threadfence();
            asm volatile("st.release.gpu.u32 [%0], %1;" ::
                         "l"(&g_sense), "r"(sense_val) : "memory");
        } else {
            unsigned v;
            do {
                asm volatile("ld.acquire.gpu.u32 %0, [%1];"
                             : "=r"(v) : "l"(&g_sense) : "memory");
            } while (v != sense_val);
        }
    }
    __syncthreads();
}

// ---------------- async-copy / mma helpers ----------------
__device__ __forceinline__ void cp_async16(void* dst_smem, const void* src_gmem) {
    unsigned d = (unsigned)__cvta_generic_to_shared(dst_smem);
    asm volatile("cp.async.cg.shared.global [%0], [%1], 16;\n"
                 :: "r"(d), "l"(src_gmem));
}
#define CP_COMMIT() asm volatile("cp.async.commit_group;\n" ::: "memory")
#define CP_WAIT0()  asm volatile("cp.async.wait_group 0;\n" ::: "memory")
#define CP_WAIT1()  asm volatile("cp.async.wait_group 1;\n" ::: "memory")

__device__ __forceinline__ void ldsm4(uint32_t* r, const __nv_bfloat16* p) {
    uint32_t a = (uint32_t)__cvta_generic_to_shared(p);
    asm volatile("ldmatrix.sync.aligned.m8n8.x4.shared.b16 {%0,%1,%2,%3}, [%4];"
                 : "=r"(r[0]), "=r"(r[1]), "=r"(r[2]), "=r"(r[3]) : "r"(a));
}

__device__ __forceinline__ void mma16816(float* d, const uint32_t* a, const uint32_t* b) {
    asm volatile(
        "mma.sync.aligned.m16n8k16.row.col.f32.bf16.bf16.f32 "
        "{%0,%1,%2,%3}, {%4,%5,%6,%7}, {%8,%9}, {%0,%1,%2,%3};"
        : "+f"(d[0]), "+f"(d[1]), "+f"(d[2]), "+f"(d[3])
        : "r"(a[0]), "r"(a[1]), "r"(a[2]), "r"(a[3]), "r"(b[0]), "r"(b[1]));
}

// ---------------- fp32 -> bf16 hi/lo split ----------------
__global__ __launch_bounds__(256) void split_kernel(
    const float4* __restrict__ src,
    __nv_bfloat162* __restrict__ hi, __nv_bfloat162* __restrict__ lo, int n4)
{
    int i = blockIdx.x * blockDim.x + threadIdx.x;
    if (i >= n4) return;
    float4 v = src[i];
    float xs[4] = {v.x, v.y, v.z, v.w};
    __nv_bfloat16 h[4], l[4];
#pragma unroll
    for (int k = 0; k < 4; k++) {
        h[k] = __float2bfloat16(xs[k]);
        l[k] = __float2bfloat16(xs[k] - __bfloat162float(h[k]));
    }
    __nv_bfloat162 h0; h0.x = h[0]; h0.y = h[1];
    __nv_bfloat162 h1; h1.x = h[2]; h1.y = h[3];
    __nv_bfloat162 l0; l0.x = l[0]; l0.y = l[1];
    __nv_bfloat162 l1; l1.x = l[2]; l1.y = l[3];
    hi[2 * i] = h0; hi[2 * i + 1] = h1;
    lo[2 * i] = l0; lo[2 * i + 1] = l1;
}

// ---------------- tensor-core input-projection GEMM ----------------
// C[M,2048] = A[M,K] @ W[2048,K]^T + bias0 + bias1, bf16 hi/lo split.
// Block tile 128x128, BK=32, 256 threads (8 warps, 2m x 4n, warp 64x32).
__global__ void __launch_bounds__(256, 1) gemm_tc(
    float* __restrict__ C,
    const __nv_bfloat16* __restrict__ Ah, const __nv_bfloat16* __restrict__ Al,
    const __nv_bfloat16* __restrict__ Wh, const __nv_bfloat16* __restrict__ Wl,
    int K, const float* __restrict__ bias0, const float* __restrict__ bias1)
{
    extern __shared__ __nv_bfloat16 sm[];
    const int ARR = 128 * 40;        // one 128x32 tile, row stride 40 (80B)
    const int STG = 4 * ARR;         // Ah, Al, Wh, Wl
    const int tid = threadIdx.x;
    const int lane = tid & 31, wid = tid >> 5;
    const int wm = wid & 1, wn = wid >> 1;
    const int bn = blockIdx.x, bm = blockIdx.y;

    const __nv_bfloat16* g0 = Ah + (size_t)(bm * 128) * K;
    const __nv_bfloat16* g1 = Al + (size_t)(bm * 128) * K;
    const __nv_bfloat16* g2 = Wh + (size_t)(bn * 128) * K;
    const __nv_bfloat16* g3 = Wl + (size_t)(bn * 128) * K;
    const __nv_bfloat16* gsrc[4] = {g0, g1, g2, g3};

    const int l_r = tid >> 2;        // 0..63
    const int l_c = tid & 3;         // 16B chunk

#define LOAD_STAGE(buf, kt)                                                     \
    {                                                                           \
        _Pragma("unroll")                                                       \
        for (int p = 0; p < 8; p++) {                                           \
            const int arr = p >> 1;                                             \
            const int r = (p & 1) * 64 + l_r;                                   \
            const void* s = gsrc[arr] + (size_t)r * K + (kt) + l_c * 8;         \
            void* d = (char*)(sm + (buf) * STG + arr * ARR + r * 40) + l_c * 16;\
            cp_async16(d, s);                                                   \
        }                                                                       \
        CP_COMMIT();                                                            \
    }

    float acc[4][4][4] = {};
    const int nk = K / 32;

    LOAD_STAGE(0, 0);

    const int a_lrow = (lane < 16) ? lane : lane - 16;
    const int a_cb = (lane < 16) ? 0 : 8;
    const int bgrp = lane >> 3, bwi = lane & 7;
    const int b_nrow = ((bgrp >= 2) ? 8 : 0) + bwi;
    const int b_koff = (bgrp & 1) ? 8 : 0;

    for (int it = 0; it < nk; it++) {
        if (it + 1 < nk) {
            LOAD_STAGE((it + 1) & 1, (it + 1) * 32);
            CP_WAIT1();
        } else {
            CP_WAIT0();
        }
        __syncthreads();
        const __nv_bfloat16* S = sm + (it & 1) * STG;

#pragma unroll
        for (int kk = 0; kk < 32; kk += 16) {
            uint32_t ah[4][4], al[4][4];
#pragma unroll
            for (int mt = 0; mt < 4; mt++) {
                int row = wm * 64 + mt * 16 + a_lrow;
                ldsm4(ah[mt], S + row * 40 + kk + a_cb);
                ldsm4(al[mt], S + ARR + row * 40 + kk + a_cb);
            }
            uint32_t bh[4][2], bl[4][2];
#pragma unroll
            for (int pr = 0; pr < 2; pr++) {
                int nrow = wn * 32 + pr * 16 + b_nrow;
                uint32_t r[4];
                ldsm4(r, S + 2 * ARR + nrow * 40 + kk + b_koff);
                bh[pr * 2][0] = r[0]; bh[pr * 2][1] = r[1];
                bh[pr * 2 + 1][0] = r[2]; bh[pr * 2 + 1][1] = r[3];
                ldsm4(r, S + 3 * ARR + nrow * 40 + kk + b_koff);
                bl[pr * 2][0] = r[0]; bl[pr * 2][1] = r[1];
                bl[pr * 2 + 1][0] = r[2]; bl[pr * 2 + 1][1] = r[3];
            }
#pragma unroll
            for (int mt = 0; mt < 4; mt++)
#pragma unroll
                for (int nt = 0; nt < 4; nt++) {
                    mma16816(acc[mt][nt], ah[mt], bh[nt]);
                    mma16816(acc[mt][nt], ah[mt], bl[nt]);
                    mma16816(acc[mt][nt], al[mt], bh[nt]);
                }
        }
        __syncthreads();
    }

    // epilogue: add biases, write fp32
    const int erow = lane >> 2, ecol = (lane & 3) * 2;
#pragma unroll
    for (int mt = 0; mt < 4; mt++) {
        int gr = bm * 128 + wm * 64 + mt * 16 + erow;
#pragma unroll
        for (int nt = 0; nt < 4; nt++) {
            int gc = bn * 128 + wn * 32 + nt * 8 + ecol;
            float b0v = bias0[gc] + bias1[gc];
            float b1v = bias0[gc + 1] + bias1[gc + 1];
            float2 v0 = make_float2(acc[mt][nt][0] + b0v, acc[mt][nt][1] + b1v);
            float2 v1 = make_float2(acc[mt][nt][2] + b0v, acc[mt][nt][3] + b1v);
            *(float2*)(C + (size_t)gr * Gz + gc) = v0;
            *(float2*)(C + (size_t)(gr + 8) * Gz + gc) = v1;
        }
    }
#undef LOAD_STAGE
}

// ---------------- persistent LSTM layer (Round-4 structure) ----------------
__global__ void __launch_bounds__(NTHR, 1) lstm_layer_persist(
    const float* __restrict__ whh,          // [2048][512]
    const float* __restrict__ xg,           // [B*T][2048] (+biases)
    const float* __restrict__ hxl,
    const float* __restrict__ cxl,
    __nv_bfloat16* __restrict__ hseq_hi,    // [B*T][512] or nullptr
    __nv_bfloat16* __restrict__ hseq_lo,
    float* __restrict__ hn_out,
    float* __restrict__ cn_out)
{
    extern __shared__ float smem[];
    float* w_sT = smem;               // [128 k][64 gcl]
    float* h_s  = smem + 128 * 64;    // [128 k][64 b]

    const int tid = threadIdx.x;
    const int bid = blockIdx.x;
    const int jg = bid >> 2;
    const int ks = bid & 3;
    const int k0 = ks * 128;
    const int jgbase = jg * 16;

    for (int i = tid; i < 64 * 128; i += NTHR) {
        int gcl = i >> 7;
        int k = i & 127;
        int g = gcl >> 4, jj = gcl & 15;
        w_sT[k * 64 + gcl] = whh[(size_t)(g * 512 + jgbase + jj) * Hz + k0 + k];
    }

    const int pb_b = (tid & 255) >> 2;
    const int pb_j = bid * 4 + (tid & 3);
    float c_reg = 0.0f;
    if (tid < 256) {
        c_reg = cxl[pb_b * Hz + pb_j];
        g_HT[pb_j * Bz + pb_b] = hxl[pb_b * Hz + pb_j];
    }

    unsigned sense = 0;
    sense ^= 1; grid_barrier(sense);

    const int kh = tid >> 8;
    const int t8 = tid & 255;
    const int b0 = (t8 & 15) * 4;
    const int gcl0 = (t8 >> 4) * 4;
    const int gc_glob0 = (gcl0 >> 4) * 512 + jgbase + (gcl0 & 15);
    const int zslot = ks * 2 + kh;
    const float* wbase = w_sT + (size_t)kh * 64 * 64;
    const float* hbase = h_s  + (size_t)kh * 64 * 64;

    float hlast = 0.0f;

    for (int t = 0; t < Tz; t++) {
        {
            const float4* src = (const float4*)(g_HT + (size_t)k0 * Bz);
            float4* dst = (float4*)h_s;
#pragma unroll
            for (int i = 0; i < (128 * 64 / 4) / NTHR; i++)
                dst[tid + i * NTHR] = src[tid + i * NTHR];
        }
        __syncthreads();

        float acc[4][4] = {};
#pragma unroll 4
        for (int k = 0; k < 64; k++) {
            float4 hv = *(const float4*)(hbase + k * 64 + b0);
            float4 wv = *(const float4*)(wbase + k * 64 + gcl0);
            float hr[4] = {hv.x, hv.y, hv.z, hv.w};
            float wr[4] = {wv.x, wv.y, wv.z, wv.w};
#pragma unroll
            for (int i = 0; i < 4; i++)
#pragma unroll
                for (int j = 0; j < 4; j++)
                    acc[i][j] += wr[i] * hr[j];
        }
#pragma unroll
        for (int i = 0; i < 4; i++) {
            int gc = gc_glob0 + i;
            float4 v = make_float4(acc[i][0], acc[i][1], acc[i][2], acc[i][3]);
            *(float4*)(g_PART + ((size_t)zslot * Gz + gc) * Bz + b0) = v;
        }
        sense ^= 1; grid_barrier(sense);

        if (tid < 256) {
            const float* xr = xg + ((size_t)pb_b * Tz + t) * Gz;
            float gsum[4];
#pragma unroll
            for (int g = 0; g < 4; g++) {
                int gc = g * 512 + pb_j;
                float s = xr[gc];
#pragma unroll
                for (int z = 0; z < 8; z++)
                    s += g_PART[((size_t)z * Gz + gc) * Bz + pb_b];
                gsum[g] = s;
            }
            float ig = 1.0f / (1.0f + expf(-gsum[0]));
            float fg = 1.0f / (1.0f + expf(-gsum[1]));
            float gg = tanhf(gsum[2]);
            float og = 1.0f / (1.0f + expf(-gsum[3]));
            c_reg = fg * c_reg + ig * gg;
            float hnew = og * tanhf(c_reg);
            hlast = hnew;
            g_HT[pb_j * Bz + pb_b] = hnew;
            if (hseq_hi) {
                __nv_bfloat16 hh = __float2bfloat16(hnew);
                __nv_bfloat16 hl = __float2bfloat16(hnew - __bfloat162float(hh));
                size_t off = ((size_t)pb_b * Tz + t) * Hz + pb_j;
                hseq_hi[off] = hh;
                hseq_lo[off] = hl;
            }
        }
        sense ^= 1; grid_barrier(sense);
    }

    if (tid < 256) {
        hn_out[pb_b * Hz + pb_j] = hlast;
        cn_out[pb_b * Hz + pb_j] = c_reg;
    }

    sense ^= 1; grid_barrier(sense);   // total 1026 barriers (even)
}

// ---------------- FC head ----------------
__global__ __launch_bounds__(256) void fc_kernel(
    float* __restrict__ out, const float* __restrict__ h,
    const float* __restrict__ w, const float* __restrict__ bb)
{
    int b = blockIdx.x;
    float s = 0.0f;
    for (int k = threadIdx.x; k < Hz; k += blockDim.x)
        s += h[(size_t)b * Hz + k] * w[k];
#pragma unroll
    for (int o = 16; o > 0; o >>= 1)
        s += __shfl_xor_sync(0xFFFFFFFFu, s, o);
    __shared__ float red[8];
    int wid = threadIdx.x >> 5, lane = threadIdx.x & 31;
    if (lane == 0) red[wid] = s;
    __syncthreads();
    if (threadIdx.x == 0) {
        float t = 0.0f;
#pragma unroll
        for (int i = 0; i < 8; i++) t += red[i];
        out[b] = t + bb[0];
    }
}

extern "C" void kernel_launch(void* const* d_in, const int* in_sizes, int n_in,
                              void* d_out, int out_size) {
    (void)in_sizes; (void)n_in; (void)out_size;
    const float* x    = (const float*)d_in[0];
    const float* hx   = (const float*)d_in[1];
    const float* cx   = (const float*)d_in[2];
    const float* wih0 = (const float*)d_in[3];
    const float* whh0 = (const float*)d_in[4];
    const float* bih0 = (const float*)d_in[5];
    const float* bhh0 = (const float*)d_in[6];
    const float* wih1 = (const float*)d_in[7];
    const float* whh1 = (const float*)d_in[8];
    const float* bih1 = (const float*)d_in[9];
    const float* bhh1 = (const float*)d_in[10];
    const float* fcw  = (const float*)d_in[11];
    const float* fcb  = (const float*)d_in[12];
    float* out = (float*)d_out;

    void *vXG, *vAH, *vAL, *vWH, *vWL;
    cudaGetSymbolAddress(&vXG, g_XG);
    cudaGetSymbolAddress(&vAH, g_AH);
    cudaGetSymbolAddress(&vAL, g_AL);
    cudaGetSymbolAddress(&vWH, g_WH);
    cudaGetSymbolAddress(&vWL, g_WL);
    float* XG = (float*)vXG;
    __nv_bfloat16* AH = (__nv_bfloat16*)vAH;
    __nv_bfloat16* AL = (__nv_bfloat16*)vAL;
    __nv_bfloat16* WH = (__nv_bfloat16*)vWH;
    __nv_bfloat16* WL = (__nv_bfloat16*)vWL;

    const int persist_smem = 2 * 128 * 64 * (int)sizeof(float);        // 64 KB
    const int gemm_smem = 2 * 4 * 128 * 40 * (int)sizeof(__nv_bfloat16); // 80 KB
    static bool attr_set = false;
    if (!attr_set) {
        cudaFuncSetAttribute(lstm_layer_persist,
                             cudaFuncAttributeMaxDynamicSharedMemorySize, persist_smem);
        cudaFuncSetAttribute(gemm_tc,
                             cudaFuncAttributeMaxDynamicSharedMemorySize, gemm_smem);
        attr_set = true;
    }

    // Output packing: [out(64) | hn(2*B*H) | cn(2*B*H)]
    float* hn = out + Bz;
    float* cn = out + Bz + 2 * BHs;

    // ---- Layer 0: split x & w_ih_0, TC GEMM, recurrence ----
    {
        int n4 = (BTz * Iz) / 4;
        split_kernel<<<(n4 + 255) / 256, 256>>>(
            (const float4*)x, (__nv_bfloat162*)AH, (__nv_bfloat162*)AL, n4);
    }
    {
        int n4 = (Gz * Iz) / 4;
        split_kernel<<<(n4 + 255) / 256, 256>>>(
            (const float4*)wih0, (__nv_bfloat162*)WH, (__nv_bfloat162*)WL, n4);
    }
    gemm_tc<<<dim3(Gz / 128, BTz / 128), 256, gemm_smem>>>(
        XG, AH, AL, WH, WL, Iz, bih0, bhh0);
    lstm_layer_persist<<<NBLK, NTHR, persist_smem>>>(
        whh0, XG, hx, cx, AH, AL, hn, cn);   // writes hseq split into AH/AL

    // ---- Layer 1 ----
    {
        int n4 = (Gz * Hz) / 4;
        split_kernel<<<(n4 + 255) / 256, 256>>>(
            (const float4*)wih1, (__nv_bfloat162*)WH, (__nv_bfloat162*)WL, n4);
    }
    gemm_tc<<<dim3(Gz / 128, BTz / 128), 256, gemm_smem>>>(
        XG, AH, AL, WH, WL, Hz, bih1, bhh1);
    lstm_layer_persist<<<NBLK, NTHR, persist_smem>>>(
        whh1, XG, hx + BHs, cx + BHs, nullptr, nullptr, hn + BHs, cn + BHs);

    // ---- FC head ----
    fc_kernel<<<Bz, 256>>>(out, hn + BHs, fcw, fcb);
}

// round 9
// speedup vs baseline: 1.7188x; 1.7147x over previous
#include <cuda_runtime.h>
#include <cuda_bf16.h>
#include <cstdint>

#define Bz 64
#define Tz 512
#define Iz 128
#define Hz 512
#define Gz 2048          // 4*H
#define BTz (Bz*Tz)      // 32768
#define BHs (Bz*Hz)      // 32768

#define NBLK 128
#define PNT 256          // persistent kernel threads

// Scratch (static device globals)
__device__ float g_XG[(size_t)BTz * Gz];            // 256 MiB: gate projections
__device__ __nv_bfloat16 g_AH[(size_t)BTz * Hz];    // 32 MiB: A hi (x-split, then hseq)
__device__ __nv_bfloat16 g_AL[(size_t)BTz * Hz];    // 32 MiB: A lo
__device__ __nv_bfloat16 g_WH[(size_t)Gz * Hz];     // 2 MiB: w_ih hi
__device__ __nv_bfloat16 g_WL[(size_t)Gz * Hz];     // 2 MiB: w_ih lo
__device__ __nv_bfloat16 g_W2H[(size_t)Gz * Hz];    // 2 MiB: w_hh hi
__device__ __nv_bfloat16 g_W2L[(size_t)Gz * Hz];    // 2 MiB: w_hh lo
__device__ __nv_bfloat16 g_HTH[2][BHs];             // double-buffered h hi [b][k]
__device__ __nv_bfloat16 g_HTL[2][BHs];             // double-buffered h lo
__device__ unsigned g_count;
__device__ unsigned g_sense;

// ---------------- grid barrier (sense reversal) ----------------
__device__ __forceinline__ void grid_barrier(unsigned sense_val) {
    __syncthreads();
    if (threadIdx.x == 0) {
        __threadfence();
        unsigned arr = atomicAdd(&g_count, 1u);
        if (arr == NBLK - 1) {
            g_count = 0;
            __threadfence();
            asm volatile("st.release.gpu.u32 [%0], %1;" ::
                         "l"(&g_sense), "r"(sense_val) : "memory");
        } else {
            unsigned v;
            do {
                asm volatile("ld.acquire.gpu.u32 %0, [%1];"
                             : "=r"(v) : "l"(&g_sense) : "memory");
            } while (v != sense_val);
        }
    }
    __syncthreads();
}

// ---------------- async-copy / mma helpers ----------------
__device__ __forceinline__ void cp_async16(void* dst_smem, const void* src_gmem) {
    unsigned d = (unsigned)__cvta_generic_to_shared(dst_smem);
    asm volatile("cp.async.cg.shared.global [%0], [%1], 16;\n"
                 :: "r"(d), "l"(src_gmem));
}
#define CP_COMMIT() asm volatile("cp.async.commit_group;\n" ::: "memory")
#define CP_WAIT0()  asm volatile("cp.async.wait_group 0;\n" ::: "memory")
#define CP_WAIT1()  asm volatile("cp.async.wait_group 1;\n" ::: "memory")

__device__ __forceinline__ void ldsm4(uint32_t* r, const __nv_bfloat16* p) {
    uint32_t a = (uint32_t)__cvta_generic_to_shared(p);
    asm volatile("ldmatrix.sync.aligned.m8n8.x4.shared.b16 {%0,%1,%2,%3}, [%4];"
                 : "=r"(r[0]), "=r"(r[1]), "=r"(r[2]), "=r"(r[3]) : "r"(a));
}

__device__ __forceinline__ void mma16816(float* d, const uint32_t* a, const uint32_t* b) {
    asm volatile(
        "mma.sync.aligned.m16n8k16.row.col.f32.bf16.bf16.f32 "
        "{%0,%1,%2,%3}, {%4,%5,%6,%7}, {%8,%9}, {%0,%1,%2,%3};"
        : "+f"(d[0]), "+f"(d[1]), "+f"(d[2]), "+f"(d[3])
        : "r"(a[0]), "r"(a[1]), "r"(a[2]), "r"(a[3]), "r"(b[0]), "r"(b[1]));
}

// ---------------- fp32 -> bf16 hi/lo split ----------------
__global__ __launch_bounds__(256) void split_kernel(
    const float4* __restrict__ src,
    __nv_bfloat162* __restrict__ hi, __nv_bfloat162* __restrict__ lo, int n4)
{
    int i = blockIdx.x * blockDim.x + threadIdx.x;
    if (i >= n4) return;
    float4 v = src[i];
    float xs[4] = {v.x, v.y, v.z, v.w};
    __nv_bfloat16 h[4], l[4];
#pragma unroll
    for (int k = 0; k < 4; k++) {
        h[k] = __float2bfloat16(xs[k]);
        l[k] = __float2bfloat16(xs[k] - __bfloat162float(h[k]));
    }
    __nv_bfloat162 h0; h0.x = h[0]; h0.y = h[1];
    __nv_bfloat162 h1; h1.x = h[2]; h1.y = h[3];
    __nv_bfloat162 l0; l0.x = l[0]; l0.y = l[1];
    __nv_bfloat162 l1; l1.x = l[2]; l1.y = l[3];
    hi[2 * i] = h0; hi[2 * i + 1] = h1;
    lo[2 * i] = l0; lo[2 * i + 1] = l1;
}

// ---------------- tensor-core input-projection GEMM (validated R8) ----------------
__global__ void __launch_bounds__(256, 1) gemm_tc(
    float* __restrict__ C,
    const __nv_bfloat16* __restrict__ Ah, const __nv_bfloat16* __restrict__ Al,
    const __nv_bfloat16* __restrict__ Wh, const __nv_bfloat16* __restrict__ Wl,
    int K, const float* __restrict__ bias0, const float* __restrict__ bias1)
{
    extern __shared__ __nv_bfloat16 sm[];
    const int ARR = 128 * 40;
    const int STG = 4 * ARR;
    const int tid = threadIdx.x;
    const int lane = tid & 31, wid = tid >> 5;
    const int wm = wid & 1, wn = wid >> 1;
    const int bn = blockIdx.x, bm = blockIdx.y;

    const __nv_bfloat16* g0 = Ah + (size_t)(bm * 128) * K;
    const __nv_bfloat16* g1 = Al + (size_t)(bm * 128) * K;
    const __nv_bfloat16* g2 = Wh + (size_t)(bn * 128) * K;
    const __nv_bfloat16* g3 = Wl + (size_t)(bn * 128) * K;
    const __nv_bfloat16* gsrc[4] = {g0, g1, g2, g3};

    const int l_r = tid >> 2;
    const int l_c = tid & 3;

#define LOAD_STAGE(buf, kt)                                                     \
    {                                                                           \
        _Pragma("unroll")                                                       \
        for (int p = 0; p < 8; p++) {                                           \
            const int arr = p >> 1;                                             \
            const int r = (p & 1) * 64 + l_r;                                   \
            const void* s = gsrc[arr] + (size_t)r * K + (kt) + l_c * 8;         \
            void* d = (char*)(sm + (buf) * STG + arr * ARR + r * 40) + l_c * 16;\
            cp_async16(d, s);                                                   \
        }                                                                       \
        CP_COMMIT();                                                            \
    }

    float acc[4][4][4] = {};
    const int nk = K / 32;

    LOAD_STAGE(0, 0);

    const int a_lrow = (lane < 16) ? lane : lane - 16;
    const int a_cb = (lane < 16) ? 0 : 8;
    const int bgrp = lane >> 3, bwi = lane & 7;
    const int b_nrow = ((bgrp >= 2) ? 8 : 0) + bwi;
    const int b_koff = (bgrp & 1) ? 8 : 0;

    for (int it = 0; it < nk; it++) {
        if (it + 1 < nk) {
            LOAD_STAGE((it + 1) & 1, (it + 1) * 32);
            CP_WAIT1();
        } else {
            CP_WAIT0();
        }
        __syncthreads();
        const __nv_bfloat16* S = sm + (it & 1) * STG;

#pragma unroll
        for (int kk = 0; kk < 32; kk += 16) {
            uint32_t ah[4][4], al[4][4];
#pragma unroll
            for (int mt = 0; mt < 4; mt++) {
                int row = wm * 64 + mt * 16 + a_lrow;
                ldsm4(ah[mt], S + row * 40 + kk + a_cb);
                ldsm4(al[mt], S + ARR + row * 40 + kk + a_cb);
            }
            uint32_t bh[4][2], bl[4][2];
#pragma unroll
            for (int pr = 0; pr < 2; pr++) {
                int nrow = wn * 32 + pr * 16 + b_nrow;
                uint32_t r[4];
                ldsm4(r, S + 2 * ARR + nrow * 40 + kk + b_koff);
                bh[pr * 2][0] = r[0]; bh[pr * 2][1] = r[1];
                bh[pr * 2 + 1][0] = r[2]; bh[pr * 2 + 1][1] = r[3];
                ldsm4(r, S + 3 * ARR + nrow * 40 + kk + b_koff);
                bl[pr * 2][0] = r[0]; bl[pr * 2][1] = r[1];
                bl[pr * 2 + 1][0] = r[2]; bl[pr * 2 + 1][1] = r[3];
            }
#pragma unroll
            for (int mt = 0; mt < 4; mt++)
#pragma unroll
                for (int nt = 0; nt < 4; nt++) {
                    mma16816(acc[mt][nt], ah[mt], bh[nt]);
                    mma16816(acc[mt][nt], ah[mt], bl[nt]);
                    mma16816(acc[mt][nt], al[mt], bh[nt]);
                }
        }
        __syncthreads();
    }

    const int erow = lane >> 2, ecol = (lane & 3) * 2;
#pragma unroll
    for (int mt = 0; mt < 4; mt++) {
        int gr = bm * 128 + wm * 64 + mt * 16 + erow;
#pragma unroll
        for (int nt = 0; nt < 4; nt++) {
            int gc = bn * 128 + wn * 32 + nt * 8 + ecol;
            float b0v = bias0[gc] + bias1[gc];
            float b1v = bias0[gc + 1] + bias1[gc + 1];
            float2 v0 = make_float2(acc[mt][nt][0] + b0v, acc[mt][nt][1] + b1v);
            float2 v1 = make_float2(acc[mt][nt][2] + b0v, acc[mt][nt][3] + b1v);
            *(float2*)(C + (size_t)gr * Gz + gc) = v0;
            *(float2*)(C + (size_t)(gr + 8) * Gz + gc) = v1;
        }
    }
#undef LOAD_STAGE
}

// ---------------- tensor-core persistent LSTM layer ----------------
// 128 blocks x 256 threads. Block (bg = bid>>5, jg = bid&31) owns batches
// [bg*16, bg*16+16) x j-cols [jg*16, jg*16+16)  -> cell fully block-local.
// Gate cols q = g*16+jj <-> global gc = g*512 + jg*16 + jj.
// w_hh hi/lo slice (64 q-rows x 512 k) cached in SMEM for the whole launch.
// Per step: cp.async gather of 16 h rows (hi+lo, buf p), bf16 hi/lo 3-pass
// mma (8 warps = 2 k-halves x 4 gate groups), smem reduce, cell update,
// h' written to buf p^1, ONE grid barrier.
__global__ void __launch_bounds__(PNT, 1) lstm_layer_tc(
    const __nv_bfloat16* __restrict__ wqh,   // [2048][512] w_hh hi
    const __nv_bfloat16* __restrict__ wql,   // lo
    const float* __restrict__ xg,            // [B*T][2048] (+biases)
    const float* __restrict__ hxl, const float* __restrict__ cxl,
    __nv_bfloat16* __restrict__ hseq_hi,     // [B*T][512] or nullptr
    __nv_bfloat16* __restrict__ hseq_lo,
    float* __restrict__ hn_out, float* __restrict__ cn_out)
{
    extern __shared__ __nv_bfloat16 sm[];
    __nv_bfloat16* w_hi = sm;                 // [64 q][520]   65 KB
    __nv_bfloat16* w_lo = sm + 64 * 520;      //               65 KB
    __nv_bfloat16* h_hi = sm + 128 * 520;     // [16 b][520]   16.25 KB
    __nv_bfloat16* h_lo = sm + 144 * 520;     //               16.25 KB
    float* acc_s = (float*)(sm + 160 * 520);  // [2 kh][64 q][16 b]  8 KB

    const int tid = threadIdx.x;
    const int bid = blockIdx.x;
    const int bg = bid >> 5;
    const int jg = bid & 31;
    const int lane = tid & 31, wid = tid >> 5;
    const int kh = wid & 1, ng = wid >> 1;

    // ---- load w_hh slice (hi+lo) via cp.async: 64 rows x 64 16B-chunks x 2 ----
    for (int i = tid; i < 8192; i += PNT) {
        int arr = i >> 12;                 // 0 = hi, 1 = lo
        int idx = i & 4095;
        int q = idx >> 6, c = idx & 63;
        int gr = (q >> 4) * 512 + jg * 16 + (q & 15);
        const __nv_bfloat16* src = (arr ? wql : wqh) + (size_t)gr * Hz + c * 8;
        __nv_bfloat16* dst = (arr ? w_lo : w_hi) + q * 520 + c * 8;
        cp_async16(dst, src);
    }
    CP_COMMIT();

    // ---- cell identity + init state ----
    const int b_loc = tid & 15, jj = tid >> 4;
    const int b_glob = bg * 16 + b_loc;
    const int j_glob = jg * 16 + jj;
    float c_reg = cxl[b_glob * Hz + j_glob];
    {
        float h0 = hxl[b_glob * Hz + j_glob];
        __nv_bfloat16 hh = __float2bfloat16(h0);
        __nv_bfloat16 hl = __float2bfloat16(h0 - __bfloat162float(hh));
        g_HTH[0][b_glob * Hz + j_glob] = hh;
        g_HTL[0][b_glob * Hz + j_glob] = hl;
    }
    CP_WAIT0();
    unsigned sense = 0;
    sense ^= 1; grid_barrier(sense);        // init h + w visible

    // ---- fragment identities (identical to validated gemm_tc) ----
    const int a_lrow = (lane < 16) ? lane : lane - 16;
    const int a_cb = (lane < 16) ? 0 : 8;
    const int bgrp = lane >> 3, bwi = lane & 7;
    const int b_nrow = ((bgrp >= 2) ? 8 : 0) + bwi;
    const int b_koff = (bgrp & 1) ? 8 : 0;
    const int erow = lane >> 2, ecol = (lane & 3) * 2;

    const __nv_bfloat16* wrow_hi = w_hi + (ng * 16 + b_nrow) * 520 + b_koff;
    const __nv_bfloat16* wrow_lo = w_lo + (ng * 16 + b_nrow) * 520 + b_koff;
    const __nv_bfloat16* arow_hi = h_hi + a_lrow * 520 + a_cb;
    const __nv_bfloat16* arow_lo = h_lo + a_lrow * 520 + a_cb;

    float hlast = 0.0f;

    for (int t = 0; t < Tz; t++) {
        const int p = t & 1;

        // ---- gather h rows for this batch group (hi+lo): 2048 x 16B ----
        {
            const __nv_bfloat16* srcH = g_HTH[p] + (size_t)(bg * 16) * Hz;
            const __nv_bfloat16* srcL = g_HTL[p] + (size_t)(bg * 16) * Hz;
#pragma unroll
            for (int i = 0; i < 8; i++) {
                int idx = tid + i * PNT;           // 0..2047
                int a = idx >> 10;                 // 0 hi, 1 lo
                int r = (idx & 1023) >> 6, c = idx & 63;
                const __nv_bfloat16* s = (a ? srcL : srcH) + r * Hz + c * 8;
                __nv_bfloat16* d = (a ? h_lo : h_hi) + r * 520 + c * 8;
                cp_async16(d, s);
            }
            CP_COMMIT();
        }

        // ---- prefetch xg (hidden under the copy) ----
        float xp[4];
#pragma unroll
        for (int g = 0; g < 4; g++)
            xp[g] = xg[((size_t)b_glob * Tz + t) * Gz + g * 512 + j_glob];

        CP_WAIT0();
        __syncthreads();

        // ---- mma: M=16, N=16 (2 n-tiles), K=256 per warp, 3 passes ----
        float acc0[4] = {}, acc1[4] = {};
        const int kbase = kh * 256;
#pragma unroll
        for (int ks = 0; ks < 16; ks++) {
            int k = kbase + ks * 16;
            uint32_t ah[4], al[4], rh[4], rl[4];
            ldsm4(ah, arow_hi + k);
            ldsm4(al, arow_lo + k);
            ldsm4(rh, wrow_hi + k);
            ldsm4(rl, wrow_lo + k);
            uint32_t bh0[2] = {rh[0], rh[1]}, bh1[2] = {rh[2], rh[3]};
            uint32_t bl0[2] = {rl[0], rl[1]}, bl1[2] = {rl[2], rl[3]};
            mma16816(acc0, ah, bh0);
            mma16816(acc0, ah, bl0);
            mma16816(acc0, al, bh0);
            mma16816(acc1, ah, bh1);
            mma16816(acc1, ah, bl1);
            mma16816(acc1, al, bh1);
        }

        // ---- stash K-half partials: acc_s[kh][q][b] ----
        {
            int q0 = ng * 16 + ecol;
            acc_s[(kh * 64 + q0) * 16 + erow]         = acc0[0];
            acc_s[(kh * 64 + q0 + 1) * 16 + erow]     = acc0[1];
            acc_s[(kh * 64 + q0) * 16 + erow + 8]     = acc0[2];
            acc_s[(kh * 64 + q0 + 1) * 16 + erow + 8] = acc0[3];
            int q1 = ng * 16 + 8 + ecol;
            acc_s[(kh * 64 + q1) * 16 + erow]         = acc1[0];
            acc_s[(kh * 64 + q1 + 1) * 16 + erow]     = acc1[1];
            acc_s[(kh * 64 + q1) * 16 + erow + 8]     = acc1[2];
            acc_s[(kh * 64 + q1 + 1) * 16 + erow + 8] = acc1[3];
        }
        __syncthreads();

        // ---- cell update (block-local) ----
        {
            float gv[4];
#pragma unroll
            for (int g = 0; g < 4; g++) {
                int q = g * 16 + jj;
                gv[g] = xp[g] + acc_s[q * 16 + b_loc] + acc_s[(64 + q) * 16 + b_loc];
            }
            float ig = 1.0f / (1.0f + expf(-gv[0]));
            float fg = 1.0f / (1.0f + expf(-gv[1]));
            float gg = tanhf(gv[2]);
            float og = 1.0f / (1.0f + expf(-gv[3]));
            c_reg = fg * c_reg + ig * gg;
            float hnew = og * tanhf(c_reg);
            hlast = hnew;
            __nv_bfloat16 hh = __float2bfloat16(hnew);
            __nv_bfloat16 hl = __float2bfloat16(hnew - __bfloat162float(hh));
            g_HTH[p ^ 1][b_glob * Hz + j_glob] = hh;
            g_HTL[p ^ 1][b_glob * Hz + j_glob] = hl;
            if (hseq_hi) {
                size_t off = ((size_t)b_glob * Tz + t) * Hz + j_glob;
                hseq_hi[off] = hh;
                hseq_lo[off] = hl;
            }
        }

        sense ^= 1; grid_barrier(sense);
    }

    hn_out[b_glob * Hz + j_glob] = hlast;
    cn_out[b_glob * Hz + j_glob] = c_reg;

    sense ^= 1; grid_barrier(sense);   // total 514 barriers (even)
}

// ---------------- FC head ----------------
__global__ __launch_bounds__(256) void fc_kernel(
    float* __restrict__ out, const float* __restrict__ h,
    const float* __restrict__ w, const float* __restrict__ bb)
{
    int b = blockIdx.x;
    float s = 0.0f;
    for (int k = threadIdx.x; k < Hz; k += blockDim.x)
        s += h[(size_t)b * Hz + k] * w[k];
#pragma unroll
    for (int o = 16; o > 0; o >>= 1)
        s += __shfl_xor_sync(0xFFFFFFFFu, s, o);
    __shared__ float red[8];
    int wid = threadIdx.x >> 5, lane = threadIdx.x & 31;
    if (lane == 0) red[wid] = s;
    __syncthreads();
    if (threadIdx.x == 0) {
        float t = 0.0f;
#pragma unroll
        for (int i = 0; i < 8; i++) t += red[i];
        out[b] = t + bb[0];
    }
}

extern "C" void kernel_launch(void* const* d_in, const int* in_sizes, int n_in,
                              void* d_out, int out_size) {
    (void)in_sizes; (void)n_in; (void)out_size;
    const float* x    = (const float*)d_in[0];
    const float* hx   = (const float*)d_in[1];
    const float* cx   = (const float*)d_in[2];
    const float* wih0 = (const float*)d_in[3];
    const float* whh0 = (const float*)d_in[4];
    const float* bih0 = (const float*)d_in[5];
    const float* bhh0 = (const float*)d_in[6];
    const float* wih1 = (const float*)d_in[7];
    const float* whh1 = (const float*)d_in[8];
    const float* bih1 = (const float*)d_in[9];
    const float* bhh1 = (const float*)d_in[10];
    const float* fcw  = (const float*)d_in[11];
    const float* fcb  = (const float*)d_in[12];
    float* out = (float*)d_out;

    void *vXG, *vAH, *vAL, *vWH, *vWL, *vW2H, *vW2L;
    cudaGetSymbolAddress(&vXG, g_XG);
    cudaGetSymbolAddress(&vAH, g_AH);
    cudaGetSymbolAddress(&vAL, g_AL);
    cudaGetSymbolAddress(&vWH, g_WH);
    cudaGetSymbolAddress(&vWL, g_WL);
    cudaGetSymbolAddress(&vW2H, g_W2H);
    cudaGetSymbolAddress(&vW2L, g_W2L);
    float* XG = (float*)vXG;
    __nv_bfloat16* AH = (__nv_bfloat16*)vAH;
    __nv_bfloat16* AL = (__nv_bfloat16*)vAL;
    __nv_bfloat16* WH = (__nv_bfloat16*)vWH;
    __nv_bfloat16* WL = (__nv_bfloat16*)vWL;
    __nv_bfloat16* W2H = (__nv_bfloat16*)vW2H;
    __nv_bfloat16* W2L = (__nv_bfloat16*)vW2L;

    const int gemm_smem = 2 * 4 * 128 * 40 * (int)sizeof(__nv_bfloat16);   // 80 KB
    const int persist_smem = 160 * 520 * (int)sizeof(__nv_bfloat16)
                           + 2 * 64 * 16 * (int)sizeof(float);             // ~170.5 KB
    static bool attr_set = false;
    if (!attr_set) {
        cudaFuncSetAttribute(gemm_tc,
                             cudaFuncAttributeMaxDynamicSharedMemorySize, gemm_smem);
        cudaFuncSetAttribute(lstm_layer_tc,
                             cudaFuncAttributeMaxDynamicSharedMemorySize, persist_smem);
        attr_set = true;
    }

    // Output packing: [out(64) | hn(2*B*H) | cn(2*B*H)]
    float* hn = out + Bz;
    float* cn = out + Bz + 2 * BHs;

    // ---- Layer 0 ----
    {
        int n4 = (BTz * Iz) / 4;
        split_kernel<<<(n4 + 255) / 256, 256>>>(
            (const float4*)x, (__nv_bfloat162*)AH, (__nv_bfloat162*)AL, n4);
    }
    {
        int n4 = (Gz * Iz) / 4;
        split_kernel<<<(n4 + 255) / 256, 256>>>(
            (const float4*)wih0, (__nv_bfloat162*)WH, (__nv_bfloat162*)WL, n4);
    }
    {
        int n4 = (Gz * Hz) / 4;
        split_kernel<<<(n4 + 255) / 256, 256>>>(
            (const float4*)whh0, (__nv_bfloat162*)W2H, (__nv_bfloat162*)W2L, n4);
    }
    gemm_tc<<<dim3(Gz / 128, BTz / 128), 256, gemm_smem>>>(
        XG, AH, AL, WH, WL, Iz, bih0, bhh0);
    lstm_layer_tc<<<NBLK, PNT, persist_smem>>>(
        W2H, W2L, XG, hx, cx, AH, AL, hn, cn);   // hseq -> AH/AL for GEMM1

    // ---- Layer 1 ----
    {
        int n4 = (Gz * Hz) / 4;
        split_kernel<<<(n4 + 255) / 256, 256>>>(
            (const float4*)wih1, (__nv_bfloat162*)WH, (__nv_bfloat162*)WL, n4);
        split_kernel<<<(n4 + 255) / 256, 256>>>(
            (const float4*)whh1, (__nv_bfloat162*)W2H, (__nv_bfloat162*)W2L, n4);
    }
    gemm_tc<<<dim3(Gz / 128, BTz / 128), 256, gemm_smem>>>(
        XG, AH, AL, WH, WL, Hz, bih1, bhh1);
    lstm_layer_tc<<<NBLK, PNT, persist_smem>>>(
        W2H, W2L, XG, hx + BHs, cx + BHs, nullptr, nullptr, hn + BHs, cn + BHs);

    // ---- FC head ----
    fc_kernel<<<Bz, 256>>>(out, hn + BHs, fcw, fcb);
}